// round 9
// baseline (speedup 1.0000x reference)
#include <cuda_runtime.h>
#include <stdint.h>

// out[i] = in[i] + 0.1*sqrt(2)*erfinv(u(i)), matching
// jax.random.normal(jax.random.key(42), (64,3,512,512), f32),
// jax_threefry_partitionable=True:
//   (y0,y1) = threefry2x32((0,42),(0,i));  bits = y0 ^ y1
//   f = bitcast((bits>>9)|0x3F800000) - 1;  u = fma(f, 2, LO), LO=-0.99999994
//   noise = 0.1*sqrt(2)*erfinv(u)   [Giles; central poly deg 4, scale folded]
//
// alu-pipe was the binder (irreducible SHF+LOP3 stream). This round: every
// rotation is computed as mul.wide.u32(x, 2^r) -> {x<<r, x>>(32-r)} on the
// FMA pipe (one IMAD.WIDE), then a single fused LOP3 (lo|hi)^x0 on the alu
// pipe. Multipliers arrive as opaque kernel args so ptxas can't reduce them
// back to SHF. Round-adds stay plain (ptxas alternates IMAD/IADD3 itself).

// rotl(x, r) ^ x0 with m = 2^r opaque: IMAD.WIDE (fma) + LOP3 (alu).
__device__ __forceinline__ uint32_t rotx(uint32_t x, uint32_t m, uint32_t x0) {
    unsigned long long p;
    asm("mul.wide.u32 %0, %1, %2;" : "=l"(p) : "r"(x), "r"(m));
    return (((uint32_t)p) | ((uint32_t)(p >> 32))) ^ x0;
}

struct Ms {
    uint32_t m13, m15, m26, m6, m17, m29, m16, m24;
};

// 20-round threefry2x32 on (0, ctr), v = ctr + 42 (key-injection 0 applied).
// Returns x0 ^ x1 after the final injection.
__device__ __forceinline__ uint32_t tf_bits(uint32_t v, const Ms& M) {
    // round 1 (x0 starts at 0): x0 = v; x1 = rotl(v,13)^v
    uint32_t x0 = v;
    uint32_t x1 = rotx(v, M.m13, v);
    x0 += x1;  x1 = rotx(x1, M.m15, x0);
    x0 += x1;  x1 = rotx(x1, M.m26, x0);
    x0 += x1;  x1 = rotx(x1, M.m6,  x0);
    // inj1 (x0+=42, x1+=k2+1) merged into round 5's x0-add (3-input IADD3)
    x1 += 0x1BD11BF1u;                      // k2 + 1
    x0 = x0 + 42u + x1;
    x1 = rotx(x1, M.m17, x0);
    x0 += x1;  x1 = rotx(x1, M.m29, x0);
    x0 += x1;  x1 = rotx(x1, M.m16, x0);
    x0 += x1;  x1 = rotx(x1, M.m24, x0);
    // inj2 (x0+=k2, x1+=2) merged into round 9's x0-add
    x1 += 2u;
    x0 = x0 + 0x1BD11BF0u + x1;
    x1 = rotx(x1, M.m13, x0);
    x0 += x1;  x1 = rotx(x1, M.m15, x0);
    x0 += x1;  x1 = rotx(x1, M.m26, x0);
    x0 += x1;  x1 = rotx(x1, M.m6,  x0);
    // inj3 (x0+=0, x1+=45)
    x1 += 45u;
    x0 = x0 + x1;
    x1 = rotx(x1, M.m17, x0);
    x0 += x1;  x1 = rotx(x1, M.m29, x0);
    x0 += x1;  x1 = rotx(x1, M.m16, x0);
    x0 += x1;  x1 = rotx(x1, M.m24, x0);
    // inj4 (x0+=42, x1+=k2+4) merged into round 17's x0-add
    x1 += 0x1BD11BF4u;                      // k2 + 4
    x0 = x0 + 42u + x1;
    x1 = rotx(x1, M.m13, x0);
    x0 += x1;  x1 = rotx(x1, M.m15, x0);
    x0 += x1;  x1 = rotx(x1, M.m26, x0);
    x0 += x1;  x1 = rotx(x1, M.m6,  x0);
    // final injection (x0+=k2, x1+=5), then lane XOR
    return (x0 + 0x1BD11BF0u) ^ (x1 + 5u);
}

// bits -> u in [LO, 1), LO = nextafter(-1,0); bit-exact vs reference.
__device__ __forceinline__ float bits_to_u(uint32_t y) {
    float f = __uint_as_float(__funnelshift_r(y, 0x7Fu, 9)) - 1.0f;
    return fmaf(f, 2.0f, -0.99999994f);
}

// Rare tail (t = w-2.5 >= 2.5, i.e. |u| > 0.99663): full Giles tail poly,
// 0.1*sqrt(2) folded into coefficients.
__device__ __forceinline__ float noise_tail_f(float t, float u) {
    float s = sqrtf(t + 2.5f) - 3.0f;
    float p =       -2.83145467e-05f;
    p = fmaf(p, s,   1.42766481e-05f);
    p = fmaf(p, s,   1.90824894e-04f);
    p = fmaf(p, s,  -5.19499916e-04f);
    p = fmaf(p, s,   8.11690563e-04f);
    p = fmaf(p, s,  -1.07798485e-03f);
    p = fmaf(p, s,   1.33486521e-03f);
    p = fmaf(p, s,   1.41657794e-01f);
    p = fmaf(p, s,   4.00644237e-01f);
    return p * u;
}

__global__ void __launch_bounds__(256)
noise_vec_kernel(const float4* __restrict__ in, float4* __restrict__ out,
                 int n4,
                 uint32_t m13, uint32_t m15, uint32_t m26, uint32_t m6,
                 uint32_t m17, uint32_t m29, uint32_t m16, uint32_t m24) {
    int tid = blockIdx.x * blockDim.x + threadIdx.x;
    if (tid >= n4) return;

    Ms M;
    M.m13 = m13; M.m15 = m15; M.m26 = m26; M.m6 = m6;
    M.m17 = m17; M.m29 = m29; M.m16 = m16; M.m24 = m24;

    float4 a = in[tid];
    const float* av = &a.x;
    uint32_t c42 = 4u * (uint32_t)tid + 42u;   // ctr + key-injection 0

    float u[4], t[4], o[4];
#pragma unroll
    for (int j = 0; j < 4; j++) {
        uint32_t y = tf_bits(c42 + (uint32_t)j, M);
        float uu = bits_to_u(y);
        float g = fmaf(-uu, uu, 1.0f);                // 1 - u^2, in (0, 1]
        float lg;
        asm("lg2.approx.f32 %0, %1;" : "=f"(lg) : "f"(g));
        float tt = fmaf(lg, -0.693147181f, -2.5f);    // w - 2.5
        // Central Giles poly deg 4, 0.1*sqrt(2) folded in.
        float p =        3.09122925e-05f;
        p = fmaf(p, tt, -1.77302644e-04f);
        p = fmaf(p, tt, -5.90813690e-04f);
        p = fmaf(p, tt,  3.48802861e-02f);
        p = fmaf(p, tt,  2.12331951e-01f);
        u[j] = uu; t[j] = tt;
        o[j] = fmaf(p, uu, av[j]);                    // out = a + p*u, fused
    }

    // One branch per thread for the rare tail (|u| > 0.99663).
    float mx = fmaxf(fmaxf(t[0], t[1]), fmaxf(t[2], t[3]));
    if (mx >= 2.5f) {
#pragma unroll
        for (int j = 0; j < 4; j++)
            if (t[j] >= 2.5f) o[j] = av[j] + noise_tail_f(t[j], u[j]);
    }

    float4 r;
    r.x = o[0]; r.y = o[1]; r.z = o[2]; r.w = o[3];
    out[tid] = r;
}

// Scalar fallback for n % 4 != 0 (not hit for this shape; plain rotates).
__device__ __forceinline__ uint32_t tf_bits_scalar(uint32_t v) {
#define TF_RND(r) { x0 += x1; x1 = __funnelshift_l(x1, x1, (r)) ^ x0; }
    uint32_t x0 = v;
    uint32_t x1 = __funnelshift_l(v, v, 13) ^ v;
    TF_RND(15) TF_RND(26) TF_RND(6)
    x1 += 0x1BD11BF1u; x0 = x0 + 42u + x1;
    x1 = __funnelshift_l(x1, x1, 17) ^ x0;
    TF_RND(29) TF_RND(16) TF_RND(24)
    x1 += 2u; x0 = x0 + 0x1BD11BF0u + x1;
    x1 = __funnelshift_l(x1, x1, 13) ^ x0;
    TF_RND(15) TF_RND(26) TF_RND(6)
    x1 += 45u; x0 = x0 + x1;
    x1 = __funnelshift_l(x1, x1, 17) ^ x0;
    TF_RND(29) TF_RND(16) TF_RND(24)
    x1 += 0x1BD11BF4u; x0 = x0 + 42u + x1;
    x1 = __funnelshift_l(x1, x1, 13) ^ x0;
    TF_RND(15) TF_RND(26) TF_RND(6)
    return (x0 + 0x1BD11BF0u) ^ (x1 + 5u);
#undef TF_RND
}

__global__ void noise_scalar_kernel(const float* __restrict__ in,
                                    float* __restrict__ out,
                                    unsigned int start, unsigned int n) {
    unsigned int i = start + blockIdx.x * blockDim.x + threadIdx.x;
    if (i >= n) return;
    uint32_t y = tf_bits_scalar(i + 42u);
    float u = bits_to_u(y);
    float g = fmaf(-u, u, 1.0f);
    float lg;
    asm("lg2.approx.f32 %0, %1;" : "=f"(lg) : "f"(g));
    float t = fmaf(lg, -0.693147181f, -2.5f);
    float p =        3.09122925e-05f;
    p = fmaf(p, t,  -1.77302644e-04f);
    p = fmaf(p, t,  -5.90813690e-04f);
    p = fmaf(p, t,   3.48802861e-02f);
    p = fmaf(p, t,   2.12331951e-01f);
    float nz = (t < 2.5f) ? p * u : noise_tail_f(t, u);
    out[i] = in[i] + nz;
}

extern "C" void kernel_launch(void* const* d_in, const int* in_sizes, int n_in,
                              void* d_out, int out_size) {
    const float* in = (const float*)d_in[0];
    float* out = (float*)d_out;

    unsigned int n = (unsigned int)in_sizes[0];  // 50331648
    int n4 = (int)(n / 4u);                      // 12582912

    if (n4 > 0) {
        int threads = 256;
        int blocks = (n4 + threads - 1) / threads;  // 49152
        noise_vec_kernel<<<blocks, threads>>>(
            (const float4*)in, (float4*)out, n4,
            1u << 13, 1u << 15, 1u << 26, 1u << 6,
            1u << 17, 1u << 29, 1u << 16, 1u << 24);
    }
    unsigned int done = (unsigned int)n4 * 4u;
    if (done < n) {
        unsigned int rem = n - done;
        noise_scalar_kernel<<<(rem + 255) / 256, 256>>>(in, out, done, n);
    }
}

// round 10
// speedup vs baseline: 1.3445x; 1.3445x over previous
#include <cuda_runtime.h>
#include <stdint.h>

// out[i] = in[i] + 0.1*sqrt(2)*erfinv(u(i)), matching
// jax.random.normal(jax.random.key(42), (64,3,512,512), f32),
// jax_threefry_partitionable=True:
//   (y0,y1) = threefry2x32((0,42),(0,i));  bits = y0 ^ y1
//   u = fma(float(bits), 2^-31, LO), LO=-0.99999994  (I2F variant; differs
//     from ref's truncating path by <=2^-23 in u, ~1e-7 in noise)
//   noise = 0.1*sqrt(2)*erfinv(u)   [Giles; central poly deg 4, scale folded]
//
// R7 skeleton (best: 150us, alu-pipe-bound at 84%): plain adds (ptxas
// alternates IMAD/IADD3), 3-input IADD3 key injections, funnelshift rotates.
// This round: I2F-based bits->u (-1 alu slot), fused out=fma(p,u,a), and a
// guard-free exact-grid kernel.

// 20-round threefry2x32 on (0, ctr), v = ctr + 42 (key-injection 0 applied).
// Returns x0 ^ x1 after the final injection.
__device__ __forceinline__ uint32_t tf_bits(uint32_t v) {
#define TF_RND(r) { x0 += x1; x1 = __funnelshift_l(x1, x1, (r)) ^ x0; }
    // round 1 (x0 starts at 0): x0 = v; x1 = rotl(v,13)^v
    uint32_t x0 = v;
    uint32_t x1 = __funnelshift_l(v, v, 13) ^ v;
    TF_RND(15) TF_RND(26) TF_RND(6)
    // inj1 (x0+=42, x1+=k2+1) merged into round 5's x0-add (3-input IADD3)
    x1 += 0x1BD11BF1u;                      // k2 + 1
    x0 = x0 + 42u + x1;
    x1 = __funnelshift_l(x1, x1, 17) ^ x0;
    TF_RND(29) TF_RND(16) TF_RND(24)
    // inj2 (x0+=k2, x1+=2) merged into round 9's x0-add
    x1 += 2u;
    x0 = x0 + 0x1BD11BF0u + x1;
    x1 = __funnelshift_l(x1, x1, 13) ^ x0;
    TF_RND(15) TF_RND(26) TF_RND(6)
    // inj3 (x0+=0, x1+=45)
    x1 += 45u;
    x0 = x0 + x1;
    x1 = __funnelshift_l(x1, x1, 17) ^ x0;
    TF_RND(29) TF_RND(16) TF_RND(24)
    // inj4 (x0+=42, x1+=k2+4) merged into round 17's x0-add
    x1 += 0x1BD11BF4u;                      // k2 + 4
    x0 = x0 + 42u + x1;
    x1 = __funnelshift_l(x1, x1, 13) ^ x0;
    TF_RND(15) TF_RND(26) TF_RND(6)
    // final injection (x0+=k2, x1+=5), then lane XOR
    return (x0 + 0x1BD11BF0u) ^ (x1 + 5u);
#undef TF_RND
}

// bits -> u in [LO, 1): single I2F + FFMA. LO = nextafter(-1, 0).
__device__ __forceinline__ float bits_to_u(uint32_t y) {
    return fmaf((float)y, 4.656612873e-10f /* 2^-31 */, -0.99999994f);
}

// Rare tail (t = w-2.5 >= 2.5, i.e. |u| > 0.99663): full Giles tail poly,
// 0.1*sqrt(2) folded into coefficients.
__device__ __forceinline__ float noise_tail_f(float t, float u) {
    float s = sqrtf(t + 2.5f) - 3.0f;
    float p =       -2.83145467e-05f;
    p = fmaf(p, s,   1.42766481e-05f);
    p = fmaf(p, s,   1.90824894e-04f);
    p = fmaf(p, s,  -5.19499916e-04f);
    p = fmaf(p, s,   8.11690563e-04f);
    p = fmaf(p, s,  -1.07798485e-03f);
    p = fmaf(p, s,   1.33486521e-03f);
    p = fmaf(p, s,   1.41657794e-01f);
    p = fmaf(p, s,   4.00644237e-01f);
    return p * u;
}

// Shared per-thread body: 4 elements, one float4 in/out.
__device__ __forceinline__ float4 noise_body(float4 a, uint32_t c42) {
    const float* av = &a.x;
    float u[4], t[4], o[4];
#pragma unroll
    for (int j = 0; j < 4; j++) {
        uint32_t y = tf_bits(c42 + (uint32_t)j);
        float uu = bits_to_u(y);
        float g = fmaf(-uu, uu, 1.0f);                // 1 - u^2, in (0, 1]
        float lg;
        asm("lg2.approx.f32 %0, %1;" : "=f"(lg) : "f"(g));
        float tt = fmaf(lg, -0.693147181f, -2.5f);    // w - 2.5
        // Central Giles poly deg 4, 0.1*sqrt(2) folded in.
        float p =        3.09122925e-05f;
        p = fmaf(p, tt, -1.77302644e-04f);
        p = fmaf(p, tt, -5.90813690e-04f);
        p = fmaf(p, tt,  3.48802861e-02f);
        p = fmaf(p, tt,  2.12331951e-01f);
        u[j] = uu; t[j] = tt;
        o[j] = fmaf(p, uu, av[j]);                    // out = a + p*u, fused
    }
    // One branch per thread for the rare tail (|u| > 0.99663, P~1.3%/thread).
    float mx = fmaxf(fmaxf(t[0], t[1]), fmaxf(t[2], t[3]));
    if (mx >= 2.5f) {
#pragma unroll
        for (int j = 0; j < 4; j++)
            if (t[j] >= 2.5f) o[j] = av[j] + noise_tail_f(t[j], u[j]);
    }
    float4 r;
    r.x = o[0]; r.y = o[1]; r.z = o[2]; r.w = o[3];
    return r;
}

// Guard-free kernel: grid*block == n4 exactly.
__global__ void __launch_bounds__(256)
noise_vec_exact(const float4* __restrict__ in, float4* __restrict__ out) {
    int tid = blockIdx.x * blockDim.x + threadIdx.x;
    out[tid] = noise_body(in[tid], 4u * (uint32_t)tid + 42u);
}

// Guarded variant (used only if n4 % 256 != 0).
__global__ void __launch_bounds__(256)
noise_vec_guard(const float4* __restrict__ in, float4* __restrict__ out,
                int n4) {
    int tid = blockIdx.x * blockDim.x + threadIdx.x;
    if (tid >= n4) return;
    out[tid] = noise_body(in[tid], 4u * (uint32_t)tid + 42u);
}

// Scalar fallback for n % 4 != 0 (not hit for this shape).
__global__ void noise_scalar_kernel(const float* __restrict__ in,
                                    float* __restrict__ out,
                                    unsigned int start, unsigned int n) {
    unsigned int i = start + blockIdx.x * blockDim.x + threadIdx.x;
    if (i >= n) return;
    uint32_t y = tf_bits(i + 42u);
    float u = bits_to_u(y);
    float g = fmaf(-u, u, 1.0f);
    float lg;
    asm("lg2.approx.f32 %0, %1;" : "=f"(lg) : "f"(g));
    float t = fmaf(lg, -0.693147181f, -2.5f);
    float p =        3.09122925e-05f;
    p = fmaf(p, t,  -1.77302644e-04f);
    p = fmaf(p, t,  -5.90813690e-04f);
    p = fmaf(p, t,   3.48802861e-02f);
    p = fmaf(p, t,   2.12331951e-01f);
    float nz = (t < 2.5f) ? p * u : noise_tail_f(t, u);
    out[i] = in[i] + nz;
}

extern "C" void kernel_launch(void* const* d_in, const int* in_sizes, int n_in,
                              void* d_out, int out_size) {
    const float* in = (const float*)d_in[0];
    float* out = (float*)d_out;

    unsigned int n = (unsigned int)in_sizes[0];  // 50331648
    int n4 = (int)(n / 4u);                      // 12582912 = 49152 * 256

    if (n4 > 0) {
        const int threads = 256;
        if (n4 % threads == 0) {
            noise_vec_exact<<<n4 / threads, threads>>>((const float4*)in,
                                                       (float4*)out);
        } else {
            int blocks = (n4 + threads - 1) / threads;
            noise_vec_guard<<<blocks, threads>>>((const float4*)in,
                                                 (float4*)out, n4);
        }
    }
    unsigned int done = (unsigned int)n4 * 4u;
    if (done < n) {
        unsigned int rem = n - done;
        noise_scalar_kernel<<<(rem + 255) / 256, 256>>>(in, out, done, n);
    }
}

// round 11
// speedup vs baseline: 1.3486x; 1.0031x over previous
#include <cuda_runtime.h>
#include <stdint.h>

// out[i] = in[i] + 0.1*sqrt(2)*erfinv(u(i)), matching
// jax.random.normal(jax.random.key(42), (64,3,512,512), f32),
// jax_threefry_partitionable=True:
//   (y0,y1) = threefry2x32((0,42),(0,i));  bits = y0 ^ y1
//   u = fma(float(bits), 2^-31, LO), LO=-0.99999994
//   noise = 0.1*sqrt(2)*erfinv(u)  [Giles; central poly deg 4, scale folded]
//
// Pipe plan: alu pipe (SHF+LOP3, irreducible) was the 85.6% binder with issue
// at 79.7% (slack). The 20 serial round-adds are migrated to the FMA pipe as
// IMAD by writing them as x0 += x1 * one, with 'one'(=1) an opaque kernel
// arg: ptxas fuses mul+add -> IMAD and cannot strength-reduce. Key
// injections stay as fused 3-input IADD3 (2 adds for 1 alu slot).

// 20-round threefry2x32 on (0, ctr), v = ctr + 42 (key-injection 0 applied).
// Returns x0 ^ x1 after the final injection.
__device__ __forceinline__ uint32_t tf_bits(uint32_t v, uint32_t one) {
#define TF_RND(r) { x0 += x1 * one; /* IMAD, fma pipe */ \
                    x1 = __funnelshift_l(x1, x1, (r)) ^ x0; }
    // round 1 (x0 starts at 0): x0 = v; x1 = rotl(v,13)^v
    uint32_t x0 = v;
    uint32_t x1 = __funnelshift_l(v, v, 13) ^ v;
    TF_RND(15) TF_RND(26) TF_RND(6)
    // inj1 (x0+=42, x1+=k2+1) merged into round 5's x0-add (3-input IADD3)
    x1 += 0x1BD11BF1u;                      // k2 + 1
    x0 = x0 + 42u + x1;
    x1 = __funnelshift_l(x1, x1, 17) ^ x0;
    TF_RND(29) TF_RND(16) TF_RND(24)
    // inj2 (x0+=k2, x1+=2) merged into round 9's x0-add
    x1 += 2u;
    x0 = x0 + 0x1BD11BF0u + x1;
    x1 = __funnelshift_l(x1, x1, 13) ^ x0;
    TF_RND(15) TF_RND(26) TF_RND(6)
    // inj3 (x0+=0, x1+=45)
    x1 += 45u;
    x0 += x1 * one;
    x1 = __funnelshift_l(x1, x1, 17) ^ x0;
    TF_RND(29) TF_RND(16) TF_RND(24)
    // inj4 (x0+=42, x1+=k2+4) merged into round 17's x0-add
    x1 += 0x1BD11BF4u;                      // k2 + 4
    x0 = x0 + 42u + x1;
    x1 = __funnelshift_l(x1, x1, 13) ^ x0;
    TF_RND(15) TF_RND(26) TF_RND(6)
    // final injection (x0+=k2, x1+=5), then lane XOR
    return (x0 + 0x1BD11BF0u) ^ (x1 + 5u);
#undef TF_RND
}

// bits -> u in [LO, 1): single I2F + FFMA. LO = nextafter(-1, 0).
__device__ __forceinline__ float bits_to_u(uint32_t y) {
    return fmaf((float)y, 4.656612873e-10f /* 2^-31 */, -0.99999994f);
}

// Rare tail (t = w-2.5 >= 2.5, i.e. |u| > 0.99663): full Giles tail poly,
// 0.1*sqrt(2) folded into coefficients.
__device__ __forceinline__ float noise_tail_f(float t, float u) {
    float s = sqrtf(t + 2.5f) - 3.0f;
    float p =       -2.83145467e-05f;
    p = fmaf(p, s,   1.42766481e-05f);
    p = fmaf(p, s,   1.90824894e-04f);
    p = fmaf(p, s,  -5.19499916e-04f);
    p = fmaf(p, s,   8.11690563e-04f);
    p = fmaf(p, s,  -1.07798485e-03f);
    p = fmaf(p, s,   1.33486521e-03f);
    p = fmaf(p, s,   1.41657794e-01f);
    p = fmaf(p, s,   4.00644237e-01f);
    return p * u;
}

// Shared per-thread body: 4 elements, one float4 in/out.
__device__ __forceinline__ float4 noise_body(float4 a, uint32_t c42,
                                             uint32_t one) {
    const float* av = &a.x;
    float u[4], t[4], o[4];
#pragma unroll
    for (int j = 0; j < 4; j++) {
        uint32_t y = tf_bits(c42 + (uint32_t)j, one);
        float uu = bits_to_u(y);
        float g = fmaf(-uu, uu, 1.0f);                // 1 - u^2, in (0, 1]
        float lg;
        asm("lg2.approx.f32 %0, %1;" : "=f"(lg) : "f"(g));
        float tt = fmaf(lg, -0.693147181f, -2.5f);    // w - 2.5
        // Central Giles poly deg 4, 0.1*sqrt(2) folded in.
        float p =        3.09122925e-05f;
        p = fmaf(p, tt, -1.77302644e-04f);
        p = fmaf(p, tt, -5.90813690e-04f);
        p = fmaf(p, tt,  3.48802861e-02f);
        p = fmaf(p, tt,  2.12331951e-01f);
        u[j] = uu; t[j] = tt;
        o[j] = fmaf(p, uu, av[j]);                    // out = a + p*u, fused
    }
    // One branch per thread for the rare tail (|u| > 0.99663).
    float mx = fmaxf(fmaxf(t[0], t[1]), fmaxf(t[2], t[3]));
    if (mx >= 2.5f) {
#pragma unroll
        for (int j = 0; j < 4; j++)
            if (t[j] >= 2.5f) o[j] = av[j] + noise_tail_f(t[j], u[j]);
    }
    float4 r;
    r.x = o[0]; r.y = o[1]; r.z = o[2]; r.w = o[3];
    return r;
}

// Guard-free kernel: grid*block == n4 exactly.
__global__ void __launch_bounds__(256)
noise_vec_exact(const float4* __restrict__ in, float4* __restrict__ out,
                uint32_t one) {
    int tid = blockIdx.x * blockDim.x + threadIdx.x;
    out[tid] = noise_body(in[tid], 4u * (uint32_t)tid + 42u, one);
}

// Guarded variant (used only if n4 % 256 != 0).
__global__ void __launch_bounds__(256)
noise_vec_guard(const float4* __restrict__ in, float4* __restrict__ out,
                int n4, uint32_t one) {
    int tid = blockIdx.x * blockDim.x + threadIdx.x;
    if (tid >= n4) return;
    out[tid] = noise_body(in[tid], 4u * (uint32_t)tid + 42u, one);
}

// Scalar fallback for n % 4 != 0 (not hit for this shape).
__global__ void noise_scalar_kernel(const float* __restrict__ in,
                                    float* __restrict__ out,
                                    unsigned int start, unsigned int n,
                                    uint32_t one) {
    unsigned int i = start + blockIdx.x * blockDim.x + threadIdx.x;
    if (i >= n) return;
    uint32_t y = tf_bits(i + 42u, one);
    float u = bits_to_u(y);
    float g = fmaf(-u, u, 1.0f);
    float lg;
    asm("lg2.approx.f32 %0, %1;" : "=f"(lg) : "f"(g));
    float t = fmaf(lg, -0.693147181f, -2.5f);
    float p =        3.09122925e-05f;
    p = fmaf(p, t,  -1.77302644e-04f);
    p = fmaf(p, t,  -5.90813690e-04f);
    p = fmaf(p, t,   3.48802861e-02f);
    p = fmaf(p, t,   2.12331951e-01f);
    float nz = (t < 2.5f) ? p * u : noise_tail_f(t, u);
    out[i] = in[i] + nz;
}

extern "C" void kernel_launch(void* const* d_in, const int* in_sizes, int n_in,
                              void* d_out, int out_size) {
    const float* in = (const float*)d_in[0];
    float* out = (float*)d_out;

    unsigned int n = (unsigned int)in_sizes[0];  // 50331648
    int n4 = (int)(n / 4u);                      // 12582912 = 49152 * 256

    if (n4 > 0) {
        const int threads = 256;
        if (n4 % threads == 0) {
            noise_vec_exact<<<n4 / threads, threads>>>((const float4*)in,
                                                       (float4*)out, 1u);
        } else {
            int blocks = (n4 + threads - 1) / threads;
            noise_vec_guard<<<blocks, threads>>>((const float4*)in,
                                                 (float4*)out, n4, 1u);
        }
    }
    unsigned int done = (unsigned int)n4 * 4u;
    if (done < n) {
        unsigned int rem = n - done;
        noise_scalar_kernel<<<(rem + 255) / 256, 256>>>(in, out, done, n, 1u);
    }
}